// round 15
// baseline (speedup 1.0000x reference)
#include <cuda_runtime.h>
#include <cuda_fp16.h>
#include <math.h>
#include <stdint.h>

// ---------------- sizes (fixed) ----------------
#define ROWS   8192
#define DMODEL 512
#define HDH    4096
#define SEQ    1024
#define NHB    64

// ---------------- scratch ----------------------
static __device__ __half g_qk16[8388608];   // q16 [8192,512] @0, k16 @4194304
static __device__ __half g_v16[4194304];    // [8192, 512]
static __device__ __half g_wqk16[4194304];  // wqt [4096,512] @0, wkt @2097152
static __device__ __half g_wvt16[2097152];  // [4096, 512]
static __device__ __half g_wot16[2097152];  // [512, 4096]
static __device__ __half g_qkh16[67108864]; // qh [8][8192][512] @0, kh @33554432
static __device__ __half g_vht16[33554432]; // [64][512][1024]  V^T per (h,b)
static __device__ __half g_pr16[67108864];  // [64, 1024, 1024] exp(scores) fp16
static __device__ float  g_rsp[524288];     // [64][1024][8] row-sum partials
static __device__ __half g_ao16[33554432];  // [8192, 4096]
static __device__ float  g_og[4194304];     // [8192, 512]

// ---------------- helpers ----------------------
__device__ __forceinline__ uint32_t smem_u32(const void* p) {
    uint32_t a;
    asm("{ .reg .u64 t; cvta.to.shared.u64 t, %1; cvt.u32.u64 %0, t; }" : "=r"(a) : "l"(p));
    return a;
}
__device__ __forceinline__ void mma16816(
    float& c0, float& c1, float& c2, float& c3,
    uint32_t a0, uint32_t a1, uint32_t a2, uint32_t a3,
    uint32_t b0, uint32_t b1)
{
    asm volatile(
        "mma.sync.aligned.m16n8k16.row.col.f32.f16.f16.f32 "
        "{%0,%1,%2,%3}, {%4,%5,%6,%7}, {%8,%9}, {%0,%1,%2,%3};"
        : "+f"(c0), "+f"(c1), "+f"(c2), "+f"(c3)
        : "r"(a0), "r"(a1), "r"(a2), "r"(a3), "r"(b0), "r"(b1));
}
#define LDSM4(r, a) \
    asm volatile("ldmatrix.sync.aligned.m8n8.x4.shared.b16 {%0,%1,%2,%3}, [%4];" \
                 : "=r"((r)[0]), "=r"((r)[1]), "=r"((r)[2]), "=r"((r)[3]) : "r"(a))

// ---------------- fp16 tensor-core GEMM core (proven mainloop) --------------
// C[m,n] = alpha * sum_k A[m,k] * B[n,k]; A,B,C already tile-offset.
// CTA 128x128, BK=64 (128B swizzled rows), 3-stage cp.async, 256 thr,
// 8 warps (2x4), warp tile 64x32, 2 CTAs/SM.
// EPI: 0 = plain store; 1 = mask+exp+rowsum partial store; 2 = 1/rowsum scale.
#define ABYTES 16384
#define STAGEB 32768
#define NSTG   3
#define GSMEM  (NSTG * STAGEB)          // 98304 B

template <typename CT, int EPI>
__device__ __forceinline__ void gemm_core(
    const __half* __restrict__ A, int lda,
    const __half* __restrict__ B, int ldb,
    CT* __restrict__ C, int ldc,
    int K, float alpha,
    const unsigned char* __restrict__ msk, float* __restrict__ rs,
    int bx, int by, int bz, int z2, char* dyn)
{
    const int tid  = threadIdx.x;
    const int warp = tid >> 5;
    const int lane = tid & 31;
    const int g    = lane >> 2;
    const int tg   = lane & 3;
    const int wm   = (warp >> 2) * 64;
    const int wn   = (warp & 3) * 32;
    const int lr   = tid >> 3;
    const int c8   = tid & 7;

    const int la = lane & 15, ha = lane >> 4;
    const int lb = ((lane >> 4) << 3) | (lane & 7);
    const int hb = (lane >> 3) & 1;

    const uint32_t sb = smem_u32(dyn);

    float acc[4][4][4];
#pragma unroll
    for (int mi = 0; mi < 4; mi++)
#pragma unroll
        for (int ni = 0; ni < 4; ni++)
#pragma unroll
            for (int r = 0; r < 4; r++) acc[mi][ni][r] = 0.0f;

    auto issue = [&](int kc, int st) {
        const int k0 = kc << 6;
        const uint32_t sA = sb + st * STAGEB;
        const uint32_t sB = sA + ABYTES;
#pragma unroll
        for (int i = 0; i < 4; i++) {
            const int r = lr + 32 * i;
            const uint32_t d = sA + r * 128 + ((c8 ^ (r & 7)) << 4);
            const void* s = &A[(size_t)r * lda + k0 + c8 * 8];
            asm volatile("cp.async.cg.shared.global [%0], [%1], 16;" :: "r"(d), "l"(s));
        }
#pragma unroll
        for (int i = 0; i < 4; i++) {
            const int r = lr + 32 * i;
            const uint32_t d = sB + r * 128 + ((c8 ^ (r & 7)) << 4);
            const void* s = &B[(size_t)r * ldb + k0 + c8 * 8];
            asm volatile("cp.async.cg.shared.global [%0], [%1], 16;" :: "r"(d), "l"(s));
        }
        asm volatile("cp.async.commit_group;" ::: "memory");
    };

    auto compute = [&](int st) {
        const uint32_t sA = sb + st * STAGEB;
        const uint32_t sB = sA + ABYTES;
#pragma unroll
        for (int ks = 0; ks < 4; ks++) {
            uint32_t af[4][4], bf[2][4];
#pragma unroll
            for (int mi = 0; mi < 4; mi++) {
                const int rr = wm + mi * 16 + la;
                const int cc = ks * 2 + ha;
                LDSM4(af[mi], sA + rr * 128 + ((cc ^ (rr & 7)) << 4));
            }
#pragma unroll
            for (int np = 0; np < 2; np++) {
                const int rr = wn + np * 16 + lb;
                const int cc = ks * 2 + hb;
                LDSM4(bf[np], sB + rr * 128 + ((cc ^ (rr & 7)) << 4));
            }
#pragma unroll
            for (int mi = 0; mi < 4; mi++)
#pragma unroll
                for (int ni = 0; ni < 4; ni++) {
                    const int np = ni >> 1, o = (ni & 1) * 2;
                    mma16816(acc[mi][ni][0], acc[mi][ni][1], acc[mi][ni][2], acc[mi][ni][3],
                             af[mi][0], af[mi][1], af[mi][2], af[mi][3],
                             bf[np][o], bf[np][o + 1]);
                }
        }
    };

    const int NK = K >> 6;
    issue(0, 0);
    issue(1, 1);
    for (int kc = 0; kc < NK; kc++) {
        if (kc < NK - 1)
            asm volatile("cp.async.wait_group 1;" ::: "memory");
        else
            asm volatile("cp.async.wait_group 0;" ::: "memory");
        __syncthreads();
        if (kc + 2 < NK) issue(kc + 2, (kc + 2) % NSTG);
        compute(kc % NSTG);
    }

    // ---------------- epilogues ----------------
    if constexpr (EPI == 0) {
#pragma unroll
        for (int mi = 0; mi < 4; mi++) {
            const int r = wm + mi * 16 + g;
#pragma unroll
            for (int ni = 0; ni < 4; ni++) {
                const int c = wn + ni * 8 + tg * 2;
                if constexpr (sizeof(CT) == 2) {
                    *(__half2*)&C[(size_t)r * ldc + c] =
                        __floats2half2_rn(alpha * acc[mi][ni][0], alpha * acc[mi][ni][1]);
                    *(__half2*)&C[(size_t)(r + 8) * ldc + c] =
                        __floats2half2_rn(alpha * acc[mi][ni][2], alpha * acc[mi][ni][3]);
                } else {
                    *(float2*)&C[(size_t)r * ldc + c] =
                        make_float2(alpha * acc[mi][ni][0], alpha * acc[mi][ni][1]);
                    *(float2*)&C[(size_t)(r + 8) * ldc + c] =
                        make_float2(alpha * acc[mi][ni][2], alpha * acc[mi][ni][3]);
                }
            }
        }
    } else if constexpr (EPI == 1) {
        // mask + exp + fp16 store; per-x-tile row-sum partial (no atomics)
        __syncthreads();
        float* srs = (float*)dyn;
        for (int i = tid; i < 128; i += 256) srs[i] = 0.0f;
        __syncthreads();
        const int q0  = by * 128;
        const int k0v = bx * 128;
        const unsigned char* mbase =
            msk + ((size_t)(z2 * 1024 + q0) * 1024 + k0v);
#pragma unroll
        for (int mi = 0; mi < 4; mi++) {
            const int r = wm + mi * 16 + g;
            float rs0 = 0.0f, rs1 = 0.0f;
#pragma unroll
            for (int ni = 0; ni < 4; ni++) {
                const int c = wn + ni * 8 + tg * 2;
                const unsigned char* m0 = mbase + (size_t)r * 1024 + c;
                const unsigned char* m1 = m0 + (size_t)8 * 1024;
                float e0 = m0[0] ? 0.0f : __expf(alpha * acc[mi][ni][0]);
                float e1 = m0[1] ? 0.0f : __expf(alpha * acc[mi][ni][1]);
                float e2 = m1[0] ? 0.0f : __expf(alpha * acc[mi][ni][2]);
                float e3 = m1[1] ? 0.0f : __expf(alpha * acc[mi][ni][3]);
                *(__half2*)&C[(size_t)r * ldc + c]       = __floats2half2_rn(e0, e1);
                *(__half2*)&C[(size_t)(r + 8) * ldc + c] = __floats2half2_rn(e2, e3);
                rs0 += e0 + e1;
                rs1 += e2 + e3;
            }
            rs0 += __shfl_xor_sync(0xffffffffu, rs0, 1);
            rs0 += __shfl_xor_sync(0xffffffffu, rs0, 2);
            rs1 += __shfl_xor_sync(0xffffffffu, rs1, 1);
            rs1 += __shfl_xor_sync(0xffffffffu, rs1, 2);
            if (tg == 0) {
                atomicAdd(&srs[wm + mi * 16 + g], rs0);
                atomicAdd(&srs[wm + mi * 16 + g + 8], rs1);
            }
        }
        __syncthreads();
        if (tid < 128)
            rs[((size_t)bz * 1024 + q0 + tid) * 8 + bx] = srs[tid];
    } else {
        // EPI == 2: sum 8 partials per row, scale by 1/rowsum
        const float* rsb = rs + ((size_t)bz * 1024 + by * 128) * 8;
#pragma unroll
        for (int mi = 0; mi < 4; mi++) {
            const int r = wm + mi * 16 + g;
            float4 p0 = *(const float4*)&rsb[(size_t)r * 8];
            float4 p1 = *(const float4*)&rsb[(size_t)r * 8 + 4];
            const float inv0 = 1.0f / (p0.x + p0.y + p0.z + p0.w +
                                       p1.x + p1.y + p1.z + p1.w);
            float4 q0v = *(const float4*)&rsb[(size_t)(r + 8) * 8];
            float4 q1v = *(const float4*)&rsb[(size_t)(r + 8) * 8 + 4];
            const float inv1 = 1.0f / (q0v.x + q0v.y + q0v.z + q0v.w +
                                       q1v.x + q1v.y + q1v.z + q1v.w);
#pragma unroll
            for (int ni = 0; ni < 4; ni++) {
                const int c = wn + ni * 8 + tg * 2;
                *(__half2*)&C[(size_t)r * ldc + c] =
                    __floats2half2_rn(inv0 * acc[mi][ni][0], inv0 * acc[mi][ni][1]);
                *(__half2*)&C[(size_t)(r + 8) * ldc + c] =
                    __floats2half2_rn(inv1 * acc[mi][ni][2], inv1 * acc[mi][ni][3]);
            }
        }
    }
}

// ---------------- generic GEMM kernel wrapper --------------------
template <typename CT, int EPI>
__global__ __launch_bounds__(256, 2)
void k_gemm_h(
    const __half* __restrict__ A, int lda, size_t Az1, size_t Az2,
    const __half* __restrict__ B, int ldb, size_t Bz1, size_t Bz2,
    CT* __restrict__ C, int ldc, size_t Cz1, size_t Cz2,
    int K, float alpha,
    const unsigned char* __restrict__ msk, float* __restrict__ rs)
{
    extern __shared__ __align__(128) char dyn[];
    const int z1 = blockIdx.z >> 3, z2 = blockIdx.z & 7;
    const __half* Ap = A + z1 * Az1 + z2 * Az2 + (size_t)blockIdx.y * 128 * lda;
    const __half* Bp = B + z1 * Bz1 + z2 * Bz2 + (size_t)blockIdx.x * 128 * ldb;
    CT* Cp = C + z1 * Cz1 + z2 * Cz2 + (size_t)blockIdx.y * 128 * ldc
               + (size_t)blockIdx.x * 128;
    gemm_core<CT, EPI>(Ap, lda, Bp, ldb, Cp, ldc, K, alpha, msk, rs,
                       blockIdx.x, blockIdx.y, blockIdx.z, z2, dyn);
}

// ---------------- merged QKV projection kernel -------------------
// j < 4096:  Q/K proj  (z=j>>8 in [0,16): z1 sel Q/K, z2 = head;
//            by = (j>>2)&63 over M=8192, bx = j&3 over N=512)
// j >= 4096: V proj transposed (t=j-4096; z=t>>5 = h*8+b;
//            by = (t>>3)&3 over M=512, bx = t&7 over N=1024)
__global__ __launch_bounds__(256, 2)
void k_gemm_qkv(
    const __half* __restrict__ qk16, const __half* __restrict__ wqk,
    __half* __restrict__ qkh,
    const __half* __restrict__ wvt, const __half* __restrict__ v16,
    __half* __restrict__ vht)
{
    extern __shared__ __align__(128) char dyn[];
    const int j = blockIdx.x;
    const __half *Ap, *Bp;
    __half* Cp;
    int ldc;
    if (j < 4096) {
        const int z = j >> 8, r = j & 255, by = r >> 2, bx = r & 3;
        const int z1 = z >> 3, z2 = z & 7;
        Ap = qk16 + (size_t)z1 * 4194304 + (size_t)by * 128 * DMODEL;
        Bp = wqk + (size_t)z1 * 2097152 + (size_t)z2 * 512 * DMODEL
                 + (size_t)bx * 128 * DMODEL;
        Cp = qkh + (size_t)z1 * 33554432 + (size_t)z2 * ((size_t)ROWS * 512)
                 + (size_t)by * 128 * 512 + (size_t)bx * 128;
        ldc = 512;
    } else {
        const int t = j - 4096;
        const int z = t >> 5, r = t & 31, by = r >> 3, bx = r & 7;
        const int z1 = z >> 3, z2 = z & 7;          // h, b
        Ap = wvt + (size_t)z1 * (512 * DMODEL) + (size_t)by * 128 * DMODEL;
        Bp = v16 + (size_t)z2 * ((size_t)SEQ * DMODEL) + (size_t)bx * 128 * DMODEL;
        Cp = vht + (size_t)z * ((size_t)512 * SEQ)
                 + (size_t)by * 128 * SEQ + (size_t)bx * 128;
        ldc = SEQ;
    }
    gemm_core<__half, 0>(Ap, DMODEL, Bp, DMODEL, Cp, ldc, DMODEL, 1.0f,
                         nullptr, nullptr, 0, 0, 0, 0, dyn);
}

// ---------------- merged prologue: converts + weight transposes ---
// j < 12288:           fp32->fp16 convert of q/k/v  (4096 CTAs each)
// 12288 <= j < 18432:  transpose Wq/Wk/Wv [512,4096] -> [4096,512] fp16
// 18432 <= j < 20480:  transpose Wo [4096,512] -> [512,4096] fp16
__global__ __launch_bounds__(256) void k_prep(
    const float* __restrict__ q, const float* __restrict__ k,
    const float* __restrict__ v,
    const float* __restrict__ Wq, const float* __restrict__ Wk,
    const float* __restrict__ Wv, const float* __restrict__ Wo,
    __half* __restrict__ qk16, __half* __restrict__ v16,
    __half* __restrict__ wqk, __half* __restrict__ wvt,
    __half* __restrict__ wot)
{
    __shared__ float t[32][33];
    const int j = blockIdx.x, tid = threadIdx.x;
    if (j < 12288) {
        const int a = j >> 12, xi = j & 4095;
        const float* in  = (a == 0) ? q : (a == 1) ? k : v;
        __half*      out = (a == 0) ? qk16 : (a == 1) ? (qk16 + 4194304) : v16;
        const int i = (xi * 256 + tid) * 4;
        float4 vv = *(const float4*)&in[i];
        ((__half2*)(out + i))[0] = __floats2half2_rn(vv.x, vv.y);
        ((__half2*)(out + i))[1] = __floats2half2_rn(vv.z, vv.w);
    } else if (j < 18432) {
        const int tt = j - 12288;
        const int z = tt >> 11, rem = tt & 2047;
        const int bx = rem & 127, by = rem >> 7;       // grid (128, 16)
        const float* in  = (z == 0) ? Wq : (z == 1) ? Wk : Wv;
        __half*      out = (z == 0) ? wqk : (z == 1) ? (wqk + 2097152) : wvt;
        const int c0 = bx * 32, r0 = by * 32;
        const int tx = tid & 31, ty = tid >> 5;
#pragma unroll
        for (int i = 0; i < 32; i += 8)
            t[ty + i][tx] = in[(size_t)(r0 + ty + i) * HDH + c0 + tx];
        __syncthreads();
#pragma unroll
        for (int i = 0; i < 32; i += 8)
            out[(size_t)(c0 + ty + i) * DMODEL + r0 + tx] = __float2half(t[tx][ty + i]);
    } else {
        const int rem = j - 18432;
        const int bx = rem & 15, by = rem >> 4;        // grid (16, 128)
        const int c0 = bx * 32, r0 = by * 32;
        const int tx = tid & 31, ty = tid >> 5;
#pragma unroll
        for (int i = 0; i < 32; i += 8)
            t[ty + i][tx] = Wo[(size_t)(r0 + ty + i) * DMODEL + c0 + tx];
        __syncthreads();
#pragma unroll
        for (int i = 0; i < 32; i += 8)
            wot[(size_t)(c0 + ty + i) * HDH + r0 + tx] = __float2half(t[tx][ty + i]);
    }
}

// ---------------- layernorm -----------------------
__global__ __launch_bounds__(256) void k_ln(
    const float* __restrict__ X, const float* __restrict__ gamma,
    const float* __restrict__ beta, float* __restrict__ Y)
{
    const int r = blockIdx.x;
    const float* x = X + (size_t)r * DMODEL;
    const int tid = threadIdx.x;
    float v0 = x[tid];
    float v1 = x[tid + 256];
    float s  = v0 + v1;
    float ss = v0 * v0 + v1 * v1;

    __shared__ float shs[8];
    __shared__ float shss[8];
#pragma unroll
    for (int off = 16; off; off >>= 1) {
        s  += __shfl_xor_sync(0xffffffffu, s,  off);
        ss += __shfl_xor_sync(0xffffffffu, ss, off);
    }
    if ((tid & 31) == 0) { shs[tid >> 5] = s; shss[tid >> 5] = ss; }
    __syncthreads();
    s = 0.0f; ss = 0.0f;
#pragma unroll
    for (int w = 0; w < 8; w++) { s += shs[w]; ss += shss[w]; }

    const float mean = s * (1.0f / 512.0f);
    const float var  = ss * (1.0f / 512.0f) - mean * mean;
    const float rstd = rsqrtf(var + 1e-5f);

    Y[(size_t)r * DMODEL + tid]       = (v0 - mean) * rstd * gamma[tid]       + beta[tid];
    Y[(size_t)r * DMODEL + tid + 256] = (v1 - mean) * rstd * gamma[tid + 256] + beta[tid + 256];
}

// ---------------- launch --------------------------
extern "C" void kernel_launch(void* const* d_in, const int* in_sizes, int n_in,
                              void* d_out, int out_size)
{
    const float* q     = (const float*)d_in[0];
    const float* k     = (const float*)d_in[1];
    const float* v     = (const float*)d_in[2];
    const float* Wq    = (const float*)d_in[3];
    const float* Wk    = (const float*)d_in[4];
    const float* Wv    = (const float*)d_in[5];
    const float* Wo    = (const float*)d_in[6];
    const float* gamma = (const float*)d_in[7];
    const float* beta  = (const float*)d_in[8];
    const unsigned char* mask = (const unsigned char*)d_in[9];
    float* out = (float*)d_out;

    __half *qk16, *v16, *wqk, *wvt, *wot, *qkh, *vht, *pr, *ao;
    float *og, *rsp;
    cudaGetSymbolAddress((void**)&qk16, g_qk16);
    cudaGetSymbolAddress((void**)&v16,  g_v16);
    cudaGetSymbolAddress((void**)&wqk,  g_wqk16);
    cudaGetSymbolAddress((void**)&wvt,  g_wvt16);
    cudaGetSymbolAddress((void**)&wot,  g_wot16);
    cudaGetSymbolAddress((void**)&qkh,  g_qkh16);
    cudaGetSymbolAddress((void**)&vht,  g_vht16);
    cudaGetSymbolAddress((void**)&pr,   g_pr16);
    cudaGetSymbolAddress((void**)&ao,   g_ao16);
    cudaGetSymbolAddress((void**)&og,   g_og);
    cudaGetSymbolAddress((void**)&rsp,  g_rsp);

    cudaFuncSetAttribute(k_gemm_qkv, cudaFuncAttributeMaxDynamicSharedMemorySize, GSMEM);
    cudaFuncSetAttribute((k_gemm_h<__half, 1>), cudaFuncAttributeMaxDynamicSharedMemorySize, GSMEM);
    cudaFuncSetAttribute((k_gemm_h<__half, 2>), cudaFuncAttributeMaxDynamicSharedMemorySize, GSMEM);
    cudaFuncSetAttribute((k_gemm_h<float, 0>),  cudaFuncAttributeMaxDynamicSharedMemorySize, GSMEM);

    // prologue: all converts + weight transposes in one launch
    k_prep<<<20480, 256>>>(q, k, v, Wq, Wk, Wv, Wo, qk16, v16, wqk, wvt, wot);

    // Q + K + V projections, one launch (V output directly transposed)
    k_gemm_qkv<<<6144, 256, GSMEM>>>(qk16, wqk, qkh, wvt, v16, vht);

    // scores -> masked exp fp16 (pr) + row-sum partials, fused
    const float inv_temp = 1.0f / sqrtf(512.0f);
    k_gemm_h<__half, 1><<<dim3(SEQ / 128, SEQ / 128, NHB), 256, GSMEM>>>(
        qkh, 512, (size_t)ROWS * 512, (size_t)SEQ * 512,
        qkh + 33554432, 512, (size_t)ROWS * 512, (size_t)SEQ * 512,
        pr, SEQ, (size_t)8 * SEQ * SEQ, (size_t)SEQ * SEQ,
        DMODEL, inv_temp, mask, rsp);

    // PV with fused partial-sum reduction + 1/rowsum normalization
    k_gemm_h<__half, 2><<<dim3(512 / 128, SEQ / 128, NHB), 256, GSMEM>>>(
        pr, SEQ, (size_t)8 * SEQ * SEQ, (size_t)SEQ * SEQ,
        vht, SEQ, (size_t)8 * 512 * SEQ, (size_t)512 * SEQ,
        ao, HDH, 512, (size_t)SEQ * HDH,
        SEQ, 1.0f, nullptr, rsp);

    // O projection
    k_gemm_h<float, 0><<<dim3(DMODEL / 128, ROWS / 128, 1), 256, GSMEM>>>(
        ao, HDH, 0, 0, wot, HDH, 0, 0, og, DMODEL, 0, 0, HDH, 1.0f,
        nullptr, nullptr);

    // LayerNorm
    k_ln<<<ROWS, 256>>>(og, gamma, beta, out);
}

// round 16
// speedup vs baseline: 1.5055x; 1.5055x over previous
#include <cuda_runtime.h>
#include <cuda_fp16.h>
#include <math.h>
#include <stdint.h>

// ---------------- sizes (fixed) ----------------
#define ROWS   8192
#define DMODEL 512
#define HDH    4096
#define SEQ    1024
#define NHB    64

// ---------------- scratch ----------------------
static __device__ __half g_qk16[8388608];   // q16 [8192,512] @0, k16 @4194304
static __device__ __half g_v16[4194304];    // [8192, 512]
static __device__ __half g_wqk16[4194304];  // wqt [4096,512] @0, wkt @2097152
static __device__ __half g_wvt16[2097152];  // [4096, 512]
static __device__ __half g_wot16[2097152];  // [512, 4096]
static __device__ __half g_qkh16[67108864]; // qh [8][8192][512] @0, kh @33554432
static __device__ __half g_vht16[33554432]; // [64][512][1024]  V^T per (h,b)
static __device__ __half g_pr16[67108864];  // [64, 1024, 1024] exp(scores) fp16
static __device__ float  g_rsp[524288];     // [64][1024][8] row-sum partials
static __device__ __half g_ao16[33554432];  // [8192, 4096]
static __device__ float  g_og[4194304];     // [8192, 512]

// ---------------- helpers ----------------------
__device__ __forceinline__ uint32_t smem_u32(const void* p) {
    uint32_t a;
    asm("{ .reg .u64 t; cvta.to.shared.u64 t, %1; cvt.u32.u64 %0, t; }" : "=r"(a) : "l"(p));
    return a;
}
__device__ __forceinline__ void mma16816(
    float& c0, float& c1, float& c2, float& c3,
    uint32_t a0, uint32_t a1, uint32_t a2, uint32_t a3,
    uint32_t b0, uint32_t b1)
{
    asm volatile(
        "mma.sync.aligned.m16n8k16.row.col.f32.f16.f16.f32 "
        "{%0,%1,%2,%3}, {%4,%5,%6,%7}, {%8,%9}, {%0,%1,%2,%3};"
        : "+f"(c0), "+f"(c1), "+f"(c2), "+f"(c3)
        : "r"(a0), "r"(a1), "r"(a2), "r"(a3), "r"(b0), "r"(b1));
}
#define LDSM4(r, a) \
    asm volatile("ldmatrix.sync.aligned.m8n8.x4.shared.b16 {%0,%1,%2,%3}, [%4];" \
                 : "=r"((r)[0]), "=r"((r)[1]), "=r"((r)[2]), "=r"((r)[3]) : "r"(a))

// ---------------- fp16 tensor-core GEMM (R14 proven — DO NOT TOUCH) ---------
// C[m,n] = alpha * sum_k A[m,k] * B[n,k]   (both operands K-major fp16)
// CTA 128x128, BK=64 (128B swizzled rows), 3-stage cp.async, 256 thr,
// 8 warps (2x4), warp tile 64x32, 2 CTAs/SM.
// EPI: 0 = plain store; 1 = mask+exp+rowsum partial store; 2 = 1/rowsum scale.
#define ABYTES 16384
#define STAGEB 32768
#define NSTG   3
#define GSMEM  (NSTG * STAGEB)          // 98304 B

template <typename CT, int EPI>
__global__ __launch_bounds__(256, 2)
void k_gemm_h(
    const __half* __restrict__ A, int lda, size_t Az1, size_t Az2,
    const __half* __restrict__ B, int ldb, size_t Bz1, size_t Bz2,
    CT* __restrict__ C, int ldc, size_t Cz1, size_t Cz2,
    int K, float alpha,
    const unsigned char* __restrict__ msk, float* __restrict__ rs)
{
    extern __shared__ __align__(128) char dyn[];

    const int z1 = blockIdx.z >> 3, z2 = blockIdx.z & 7;
    A += z1 * Az1 + z2 * Az2 + (size_t)blockIdx.y * 128 * lda;
    B += z1 * Bz1 + z2 * Bz2 + (size_t)blockIdx.x * 128 * ldb;
    C += z1 * Cz1 + z2 * Cz2 + (size_t)blockIdx.y * 128 * ldc + (size_t)blockIdx.x * 128;

    const int tid  = threadIdx.x;
    const int warp = tid >> 5;
    const int lane = tid & 31;
    const int g    = lane >> 2;
    const int tg   = lane & 3;
    const int wm   = (warp >> 2) * 64;
    const int wn   = (warp & 3) * 32;
    const int lr   = tid >> 3;
    const int c8   = tid & 7;

    const int la = lane & 15, ha = lane >> 4;
    const int lb = ((lane >> 4) << 3) | (lane & 7);
    const int hb = (lane >> 3) & 1;

    const uint32_t sb = smem_u32(dyn);

    float acc[4][4][4];
#pragma unroll
    for (int mi = 0; mi < 4; mi++)
#pragma unroll
        for (int ni = 0; ni < 4; ni++)
#pragma unroll
            for (int r = 0; r < 4; r++) acc[mi][ni][r] = 0.0f;

    auto issue = [&](int kc, int st) {
        const int k0 = kc << 6;
        const uint32_t sA = sb + st * STAGEB;
        const uint32_t sB = sA + ABYTES;
#pragma unroll
        for (int i = 0; i < 4; i++) {
            const int r = lr + 32 * i;
            const uint32_t d = sA + r * 128 + ((c8 ^ (r & 7)) << 4);
            const void* s = &A[(size_t)r * lda + k0 + c8 * 8];
            asm volatile("cp.async.cg.shared.global [%0], [%1], 16;" :: "r"(d), "l"(s));
        }
#pragma unroll
        for (int i = 0; i < 4; i++) {
            const int r = lr + 32 * i;
            const uint32_t d = sB + r * 128 + ((c8 ^ (r & 7)) << 4);
            const void* s = &B[(size_t)r * ldb + k0 + c8 * 8];
            asm volatile("cp.async.cg.shared.global [%0], [%1], 16;" :: "r"(d), "l"(s));
        }
        asm volatile("cp.async.commit_group;" ::: "memory");
    };

    auto compute = [&](int st) {
        const uint32_t sA = sb + st * STAGEB;
        const uint32_t sB = sA + ABYTES;
#pragma unroll
        for (int ks = 0; ks < 4; ks++) {
            uint32_t af[4][4], bf[2][4];
#pragma unroll
            for (int mi = 0; mi < 4; mi++) {
                const int rr = wm + mi * 16 + la;
                const int cc = ks * 2 + ha;
                LDSM4(af[mi], sA + rr * 128 + ((cc ^ (rr & 7)) << 4));
            }
#pragma unroll
            for (int np = 0; np < 2; np++) {
                const int rr = wn + np * 16 + lb;
                const int cc = ks * 2 + hb;
                LDSM4(bf[np], sB + rr * 128 + ((cc ^ (rr & 7)) << 4));
            }
#pragma unroll
            for (int mi = 0; mi < 4; mi++)
#pragma unroll
                for (int ni = 0; ni < 4; ni++) {
                    const int np = ni >> 1, o = (ni & 1) * 2;
                    mma16816(acc[mi][ni][0], acc[mi][ni][1], acc[mi][ni][2], acc[mi][ni][3],
                             af[mi][0], af[mi][1], af[mi][2], af[mi][3],
                             bf[np][o], bf[np][o + 1]);
                }
        }
    };

    const int NK = K >> 6;
    issue(0, 0);
    issue(1, 1);
    for (int kc = 0; kc < NK; kc++) {
        if (kc < NK - 1)
            asm volatile("cp.async.wait_group 1;" ::: "memory");
        else
            asm volatile("cp.async.wait_group 0;" ::: "memory");
        __syncthreads();
        if (kc + 2 < NK) issue(kc + 2, (kc + 2) % NSTG);
        compute(kc % NSTG);
    }

    // ---------------- epilogues ----------------
    if constexpr (EPI == 0) {
#pragma unroll
        for (int mi = 0; mi < 4; mi++) {
            const int r = wm + mi * 16 + g;
#pragma unroll
            for (int ni = 0; ni < 4; ni++) {
                const int c = wn + ni * 8 + tg * 2;
                if constexpr (sizeof(CT) == 2) {
                    *(__half2*)&C[(size_t)r * ldc + c] =
                        __floats2half2_rn(alpha * acc[mi][ni][0], alpha * acc[mi][ni][1]);
                    *(__half2*)&C[(size_t)(r + 8) * ldc + c] =
                        __floats2half2_rn(alpha * acc[mi][ni][2], alpha * acc[mi][ni][3]);
                } else {
                    *(float2*)&C[(size_t)r * ldc + c] =
                        make_float2(alpha * acc[mi][ni][0], alpha * acc[mi][ni][1]);
                    *(float2*)&C[(size_t)(r + 8) * ldc + c] =
                        make_float2(alpha * acc[mi][ni][2], alpha * acc[mi][ni][3]);
                }
            }
        }
    } else if constexpr (EPI == 1) {
        // mask + exp + fp16 store; per-x-tile row-sum partial (no atomics)
        __syncthreads();
        float* srs = (float*)dyn;
        for (int i = tid; i < 128; i += 256) srs[i] = 0.0f;
        __syncthreads();
        const int q0  = blockIdx.y * 128;
        const int k0v = blockIdx.x * 128;
        const unsigned char* mbase =
            msk + ((size_t)(z2 * 1024 + q0) * 1024 + k0v);
#pragma unroll
        for (int mi = 0; mi < 4; mi++) {
            const int r = wm + mi * 16 + g;
            float rs0 = 0.0f, rs1 = 0.0f;
#pragma unroll
            for (int ni = 0; ni < 4; ni++) {
                const int c = wn + ni * 8 + tg * 2;
                const unsigned char* m0 = mbase + (size_t)r * 1024 + c;
                const unsigned char* m1 = m0 + (size_t)8 * 1024;
                float e0 = m0[0] ? 0.0f : __expf(alpha * acc[mi][ni][0]);
                float e1 = m0[1] ? 0.0f : __expf(alpha * acc[mi][ni][1]);
                float e2 = m1[0] ? 0.0f : __expf(alpha * acc[mi][ni][2]);
                float e3 = m1[1] ? 0.0f : __expf(alpha * acc[mi][ni][3]);
                *(__half2*)&C[(size_t)r * ldc + c]       = __floats2half2_rn(e0, e1);
                *(__half2*)&C[(size_t)(r + 8) * ldc + c] = __floats2half2_rn(e2, e3);
                rs0 += e0 + e1;
                rs1 += e2 + e3;
            }
            rs0 += __shfl_xor_sync(0xffffffffu, rs0, 1);
            rs0 += __shfl_xor_sync(0xffffffffu, rs0, 2);
            rs1 += __shfl_xor_sync(0xffffffffu, rs1, 1);
            rs1 += __shfl_xor_sync(0xffffffffu, rs1, 2);
            if (tg == 0) {
                atomicAdd(&srs[wm + mi * 16 + g], rs0);
                atomicAdd(&srs[wm + mi * 16 + g + 8], rs1);
            }
        }
        __syncthreads();
        if (tid < 128)
            rs[((size_t)blockIdx.z * 1024 + q0 + tid) * 8 + blockIdx.x] = srs[tid];
    } else {
        // EPI == 2: sum 8 partials per row, scale by 1/rowsum
        const float* rsb = rs + ((size_t)blockIdx.z * 1024 + blockIdx.y * 128) * 8;
#pragma unroll
        for (int mi = 0; mi < 4; mi++) {
            const int r = wm + mi * 16 + g;
            float4 p0 = *(const float4*)&rsb[(size_t)r * 8];
            float4 p1 = *(const float4*)&rsb[(size_t)r * 8 + 4];
            const float inv0 = 1.0f / (p0.x + p0.y + p0.z + p0.w +
                                       p1.x + p1.y + p1.z + p1.w);
            float4 q0v = *(const float4*)&rsb[(size_t)(r + 8) * 8];
            float4 q1v = *(const float4*)&rsb[(size_t)(r + 8) * 8 + 4];
            const float inv1 = 1.0f / (q0v.x + q0v.y + q0v.z + q0v.w +
                                       q1v.x + q1v.y + q1v.z + q1v.w);
#pragma unroll
            for (int ni = 0; ni < 4; ni++) {
                const int c = wn + ni * 8 + tg * 2;
                *(__half2*)&C[(size_t)r * ldc + c] =
                    __floats2half2_rn(inv0 * acc[mi][ni][0], inv0 * acc[mi][ni][1]);
                *(__half2*)&C[(size_t)(r + 8) * ldc + c] =
                    __floats2half2_rn(inv1 * acc[mi][ni][2], inv1 * acc[mi][ni][3]);
            }
        }
    }
}

// ---------------- merged prologue: converts + weight transposes ---
// j < 12288:           fp32->fp16 convert of q/k/v  (4096 CTAs each)
// 12288 <= j < 18432:  transpose Wq/Wk/Wv [512,4096] -> [4096,512] fp16
// 18432 <= j < 20480:  transpose Wo [4096,512] -> [512,4096] fp16
__global__ __launch_bounds__(256) void k_prep(
    const float* __restrict__ q, const float* __restrict__ k,
    const float* __restrict__ v,
    const float* __restrict__ Wq, const float* __restrict__ Wk,
    const float* __restrict__ Wv, const float* __restrict__ Wo,
    __half* __restrict__ qk16, __half* __restrict__ v16,
    __half* __restrict__ wqk, __half* __restrict__ wvt,
    __half* __restrict__ wot)
{
    __shared__ float t[32][33];
    const int j = blockIdx.x, tid = threadIdx.x;
    if (j < 12288) {
        const int a = j >> 12, xi = j & 4095;
        const float* in  = (a == 0) ? q : (a == 1) ? k : v;
        __half*      out = (a == 0) ? qk16 : (a == 1) ? (qk16 + 4194304) : v16;
        const int i = (xi * 256 + tid) * 4;
        float4 vv = *(const float4*)&in[i];
        ((__half2*)(out + i))[0] = __floats2half2_rn(vv.x, vv.y);
        ((__half2*)(out + i))[1] = __floats2half2_rn(vv.z, vv.w);
    } else if (j < 18432) {
        const int tt = j - 12288;
        const int z = tt >> 11, rem = tt & 2047;
        const int bx = rem & 127, by = rem >> 7;       // (128, 16) tiles
        const float* in  = (z == 0) ? Wq : (z == 1) ? Wk : Wv;
        __half*      out = (z == 0) ? wqk : (z == 1) ? (wqk + 2097152) : wvt;
        const int c0 = bx * 32, r0 = by * 32;
        const int tx = tid & 31, ty = tid >> 5;
#pragma unroll
        for (int i = 0; i < 32; i += 8)
            t[ty + i][tx] = in[(size_t)(r0 + ty + i) * HDH + c0 + tx];
        __syncthreads();
#pragma unroll
        for (int i = 0; i < 32; i += 8)
            out[(size_t)(c0 + ty + i) * DMODEL + r0 + tx] = __float2half(t[tx][ty + i]);
    } else {
        const int rem = j - 18432;
        const int bx = rem & 15, by = rem >> 4;        // (16, 128) tiles
        const int c0 = bx * 32, r0 = by * 32;
        const int tx = tid & 31, ty = tid >> 5;
#pragma unroll
        for (int i = 0; i < 32; i += 8)
            t[ty + i][tx] = Wo[(size_t)(r0 + ty + i) * DMODEL + c0 + tx];
        __syncthreads();
#pragma unroll
        for (int i = 0; i < 32; i += 8)
            wot[(size_t)(c0 + ty + i) * HDH + r0 + tx] = __float2half(t[tx][ty + i]);
    }
}

// ---------------- layernorm -----------------------
__global__ __launch_bounds__(256) void k_ln(
    const float* __restrict__ X, const float* __restrict__ gamma,
    const float* __restrict__ beta, float* __restrict__ Y)
{
    const int r = blockIdx.x;
    const float* x = X + (size_t)r * DMODEL;
    const int tid = threadIdx.x;
    float v0 = x[tid];
    float v1 = x[tid + 256];
    float s  = v0 + v1;
    float ss = v0 * v0 + v1 * v1;

    __shared__ float shs[8];
    __shared__ float shss[8];
#pragma unroll
    for (int off = 16; off; off >>= 1) {
        s  += __shfl_xor_sync(0xffffffffu, s,  off);
        ss += __shfl_xor_sync(0xffffffffu, ss, off);
    }
    if ((tid & 31) == 0) { shs[tid >> 5] = s; shss[tid >> 5] = ss; }
    __syncthreads();
    s = 0.0f; ss = 0.0f;
#pragma unroll
    for (int w = 0; w < 8; w++) { s += shs[w]; ss += shss[w]; }

    const float mean = s * (1.0f / 512.0f);
    const float var  = ss * (1.0f / 512.0f) - mean * mean;
    const float rstd = rsqrtf(var + 1e-5f);

    Y[(size_t)r * DMODEL + tid]       = (v0 - mean) * rstd * gamma[tid]       + beta[tid];
    Y[(size_t)r * DMODEL + tid + 256] = (v1 - mean) * rstd * gamma[tid + 256] + beta[tid + 256];
}

// ---------------- launch --------------------------
extern "C" void kernel_launch(void* const* d_in, const int* in_sizes, int n_in,
                              void* d_out, int out_size)
{
    const float* q     = (const float*)d_in[0];
    const float* k     = (const float*)d_in[1];
    const float* v     = (const float*)d_in[2];
    const float* Wq    = (const float*)d_in[3];
    const float* Wk    = (const float*)d_in[4];
    const float* Wv    = (const float*)d_in[5];
    const float* Wo    = (const float*)d_in[6];
    const float* gamma = (const float*)d_in[7];
    const float* beta  = (const float*)d_in[8];
    const unsigned char* mask = (const unsigned char*)d_in[9];
    float* out = (float*)d_out;

    __half *qk16, *v16, *wqk, *wvt, *wot, *qkh, *vht, *pr, *ao;
    float *og, *rsp;
    cudaGetSymbolAddress((void**)&qk16, g_qk16);
    cudaGetSymbolAddress((void**)&v16,  g_v16);
    cudaGetSymbolAddress((void**)&wqk,  g_wqk16);
    cudaGetSymbolAddress((void**)&wvt,  g_wvt16);
    cudaGetSymbolAddress((void**)&wot,  g_wot16);
    cudaGetSymbolAddress((void**)&qkh,  g_qkh16);
    cudaGetSymbolAddress((void**)&vht,  g_vht16);
    cudaGetSymbolAddress((void**)&pr,   g_pr16);
    cudaGetSymbolAddress((void**)&ao,   g_ao16);
    cudaGetSymbolAddress((void**)&og,   g_og);
    cudaGetSymbolAddress((void**)&rsp,  g_rsp);

    cudaFuncSetAttribute((k_gemm_h<__half, 0>), cudaFuncAttributeMaxDynamicSharedMemorySize, GSMEM);
    cudaFuncSetAttribute((k_gemm_h<__half, 1>), cudaFuncAttributeMaxDynamicSharedMemorySize, GSMEM);
    cudaFuncSetAttribute((k_gemm_h<__half, 2>), cudaFuncAttributeMaxDynamicSharedMemorySize, GSMEM);
    cudaFuncSetAttribute((k_gemm_h<float, 0>),  cudaFuncAttributeMaxDynamicSharedMemorySize, GSMEM);

    // prologue: all converts + weight transposes in one launch
    k_prep<<<20480, 256>>>(q, k, v, Wq, Wk, Wv, Wo, qk16, v16, wqk, wvt, wot);

    // Q + K projections, one launch, head-separated output.
    k_gemm_h<__half, 0><<<dim3(512 / 128, ROWS / 128, 16), 256, GSMEM>>>(
        qk16, DMODEL, 4194304, 0,
        wqk,  DMODEL, 2097152, (size_t)512 * DMODEL,
        qkh,  512, 33554432, (size_t)ROWS * 512,
        DMODEL, 1.0f, nullptr, nullptr);

    // V projection transposed: vht[h,b][d][s] = sum_k WvT[h*512+d,k] * v16[b*1024+s,k]
    k_gemm_h<__half, 0><<<dim3(SEQ / 128, 512 / 128, NHB), 256, GSMEM>>>(
        wvt, DMODEL, (size_t)512 * DMODEL, 0,
        v16, DMODEL, 0, (size_t)SEQ * DMODEL,
        vht, SEQ, (size_t)8 * 512 * SEQ, (size_t)512 * SEQ,
        DMODEL, 1.0f, nullptr, nullptr);

    // scores -> masked exp fp16 (pr) + row-sum partials, fused
    const float inv_temp = 1.0f / sqrtf(512.0f);
    k_gemm_h<__half, 1><<<dim3(SEQ / 128, SEQ / 128, NHB), 256, GSMEM>>>(
        qkh, 512, (size_t)ROWS * 512, (size_t)SEQ * 512,
        qkh + 33554432, 512, (size_t)ROWS * 512, (size_t)SEQ * 512,
        pr, SEQ, (size_t)8 * SEQ * SEQ, (size_t)SEQ * SEQ,
        DMODEL, inv_temp, mask, rsp);

    // PV with fused partial-sum reduction + 1/rowsum normalization
    k_gemm_h<__half, 2><<<dim3(512 / 128, SEQ / 128, NHB), 256, GSMEM>>>(
        pr, SEQ, (size_t)8 * SEQ * SEQ, (size_t)SEQ * SEQ,
        vht, SEQ, (size_t)8 * 512 * SEQ, (size_t)512 * SEQ,
        ao, HDH, 512, (size_t)SEQ * HDH,
        SEQ, 1.0f, nullptr, rsp);

    // O projection
    k_gemm_h<float, 0><<<dim3(DMODEL / 128, ROWS / 128, 1), 256, GSMEM>>>(
        ao, HDH, 0, 0, wot, HDH, 0, 0, og, DMODEL, 0, 0, HDH, 1.0f,
        nullptr, nullptr);

    // LayerNorm
    k_ln<<<ROWS, 256>>>(og, gamma, beta, out);
}